// round 2
// baseline (speedup 1.0000x reference)
#include <cuda_runtime.h>
#include <math.h>

#define HH 224
#define WW 224
#define NB 8
#define CQ 32

// ---------------- scratch (static device globals; no allocation) ----------------
__device__ float g_q[NB * HH * WW * CQ];     // [b][h][w][c]  ~51.4 MB
__device__ float g_hr[2][NB * 3 * HH * WW];  // ping-pong hr  ~9.6 MB
__device__ float g_src[NB * 972];            // linear output = [8][3][18][18]

// ---------------- helpers ----------------
__device__ __forceinline__ void fma2(unsigned long long &acc, unsigned long long a,
                                     unsigned long long b) {
    asm("fma.rn.f32x2 %0, %1, %2, %0;" : "+l"(acc) : "l"(a), "l"(b));
}
__device__ __forceinline__ unsigned long long pack2(float lo, float hi) {
    unsigned long long r;
    asm("mov.b64 %0, {%1,%2};" : "=l"(r) : "f"(lo), "f"(hi));
    return r;
}
__device__ __forceinline__ float2 unpack2(unsigned long long v) {
    float2 f;
    asm("mov.b64 {%0,%1}, %2;" : "=f"(f.x), "=f"(f.y) : "l"(v));
    return f;
}
__device__ __forceinline__ int refl(int i, int n) {
    if (i < 0) i = -i;
    if (i >= n) i = 2 * n - 2 - i;
    return i;
}
__device__ __forceinline__ float cubicw(float d) {
    // torch bicubic kernel, a = -0.75
    d = fabsf(d);
    float d2 = d * d, d3 = d2 * d;
    if (d <= 1.f) return 1.25f * d3 - 2.25f * d2 + 1.f;
    if (d < 2.f) return -0.75f * d3 + 3.75f * d2 - 6.f * d + 3.f;
    return 0.f;
}

// ---------------- kernel 1: linear [8,1000] @ [1000,972]^T + b ----------------
__global__ void linear_kernel(const float* __restrict__ x, const float* __restrict__ Wl,
                              const float* __restrict__ bl) {
    int wid = (blockIdx.x * blockDim.x + threadIdx.x) >> 5;
    int lane = threadIdx.x & 31;
    if (wid >= NB * 972) return;
    int b = wid / 972, j = wid % 972;
    const float* xr = x + b * 1000;
    const float* wr = Wl + j * 1000;
    float acc = 0.f;
    for (int c = lane; c < 1000; c += 32) acc += xr[c] * wr[c];
#pragma unroll
    for (int o = 16; o > 0; o >>= 1) acc += __shfl_down_sync(0xffffffffu, acc, o);
    if (lane == 0) g_src[wid] = acc + bl[j];
}

// ---------------- kernel 2: bicubic 18x18 -> 224x224 (stage 0 only) ----------------
__global__ void bicubic_kernel() {
    int idx = blockIdx.x * blockDim.x + threadIdx.x;
    if (idx >= NB * 3 * HH * WW) return;
    int w = idx % WW;
    int h = (idx / WW) % HH;
    int bc = idx / (HH * WW);  // b*3 + c

    const float scale = 18.f / 224.f;

    float xi = (w + 0.5f) * scale - 0.5f;
    int x0 = (int)floorf(xi);
    float tx = xi - (float)x0;
    float wx[4];
    int ix[4];
#pragma unroll
    for (int k = 0; k < 4; k++) {
        wx[k] = cubicw(tx - (float)(k - 1));
        int ii = x0 + k - 1;
        ix[k] = ii < 0 ? 0 : (ii > 17 ? 17 : ii);
    }
    float yi = (h + 0.5f) * scale - 0.5f;
    int y0 = (int)floorf(yi);
    float ty = yi - (float)y0;
    float wy[4];
    int iy[4];
#pragma unroll
    for (int k = 0; k < 4; k++) {
        wy[k] = cubicw(ty - (float)(k - 1));
        int ii = y0 + k - 1;
        iy[k] = ii < 0 ? 0 : (ii > 17 ? 17 : ii);
    }
    const float* s = g_src + bc * 324;
    float acc = 0.f;
#pragma unroll
    for (int ky = 0; ky < 4; ky++) {
        float rowacc = 0.f;
#pragma unroll
        for (int kx = 0; kx < 4; kx++) rowacc += wx[kx] * s[iy[ky] * 18 + ix[kx]];
        acc += wy[ky] * rowacc;
    }
    g_hr[0][idx] = acc;
}

// ---------------- kernel 3: range projection q = W2(gelu(W1 g + b1)) + b2 ----------------
__global__ void qproj_kernel(const float* __restrict__ guid, const float* __restrict__ w1,
                             const float* __restrict__ b1, const float* __restrict__ w2,
                             const float* __restrict__ b2) {
    __shared__ float s_w1[96];
    __shared__ float s_b1[32];
    __shared__ float s_b2[32];
    __shared__ unsigned long long s_w2p[512];  // [j2][k] packed (w2[2j2][k], w2[2j2+1][k])
    __shared__ float s_out[256][33];           // padded to kill bank conflicts

    int tid = threadIdx.x;
    if (tid < 96) s_w1[tid] = w1[tid];
    if (tid < 32) {
        s_b1[tid] = b1[tid];
        s_b2[tid] = b2[tid];
    }
    for (int i = tid; i < 512; i += 256) {
        int j2 = i >> 5, k = i & 31;
        s_w2p[i] = pack2(w2[(2 * j2) * 32 + k], w2[(2 * j2 + 1) * 32 + k]);
    }
    __syncthreads();

    int pix = blockIdx.x * 256 + tid;  // < 8*224*224 exactly
    int b = pix / (HH * WW);
    int hw = pix % (HH * WW);
    float g0 = guid[(b * 3 + 0) * HH * WW + hw];
    float g1 = guid[(b * 3 + 1) * HH * WW + hw];
    float g2 = guid[(b * 3 + 2) * HH * WW + hw];

    unsigned long long acc[16];
#pragma unroll
    for (int j2 = 0; j2 < 16; j2++) acc[j2] = pack2(s_b2[2 * j2], s_b2[2 * j2 + 1]);

#pragma unroll
    for (int k = 0; k < 32; k++) {
        float v = s_b1[k] + s_w1[k * 3] * g0 + s_w1[k * 3 + 1] * g1 + s_w1[k * 3 + 2] * g2;
        float h = 0.5f * v * (1.f + erff(v * 0.70710678118654752f));  // exact gelu
        unsigned long long hh = pack2(h, h);
#pragma unroll
        for (int j2 = 0; j2 < 16; j2++) fma2(acc[j2], hh, s_w2p[j2 * 32 + k]);
    }
#pragma unroll
    for (int j2 = 0; j2 < 16; j2++) {
        float2 f = unpack2(acc[j2]);
        s_out[tid][2 * j2] = f.x;
        s_out[tid][2 * j2 + 1] = f.y;
    }
    __syncthreads();
    // coalesced write: [pix][32] channel-last
    int base = blockIdx.x * 256 * 32;
#pragma unroll
    for (int i = 0; i < 32; i++) {
        int idx = i * 256 + tid;
        g_q[base + idx] = s_out[idx >> 5][idx & 31];
    }
}

// ---------------- kernel 4: JBU (scores + softmax*spatial + adaptive conv) ----------------
#define TQ_ELEMS (14 * 38 * 8)                          // float4 count
#define SMEM_JBU (TQ_ELEMS * 16 + 3 * 14 * 38 * 4)      // 74480 bytes

__global__ void __launch_bounds__(256, 2)
jbu_kernel(const float* __restrict__ temps, const float* __restrict__ sigmas, int stage,
           int srcSel, float* __restrict__ finalOut) {
    extern __shared__ float smem[];
    float4* sq = (float4*)smem;                // swizzled q tile [14][38][8]
    float* shr = smem + TQ_ELEMS * 4;          // hr tile [3][14][38]

    int tx = threadIdx.x, ty = threadIdx.y;
    int tid = ty * 32 + tx;
    int b = blockIdx.z;
    int gx0 = blockIdx.x * 32 - 3;
    int gy0 = blockIdx.y * 8 - 3;

    // --- load q tile (reflect-padded), XOR swizzle on c4 by col&7 ---
    const float* qsrc = g_q + b * (HH * WW * CQ);
    for (int idx = tid; idx < TQ_ELEMS; idx += 256) {
        int c4 = idx & 7;
        int col = (idx >> 3) % 38;
        int r = idx / (38 * 8);
        int gr = refl(gy0 + r, HH);
        int gc = refl(gx0 + col, WW);
        float4 v = *(const float4*)(qsrc + (gr * WW + gc) * CQ + c4 * 4);
        sq[(r * 38 + col) * 8 + (c4 ^ (col & 7))] = v;
    }
    // --- load hr tile (reflect-padded) ---
    const float* hsrc = g_hr[srcSel] + b * 3 * HH * WW;
    for (int idx = tid; idx < 3 * 14 * 38; idx += 256) {
        int col = idx % 38;
        int r = (idx / 38) % 14;
        int c = idx / (38 * 14);
        int gr = refl(gy0 + r, HH);
        int gc = refl(gx0 + col, WW);
        shr[(c * 14 + r) * 38 + col] = hsrc[c * HH * WW + gr * WW + gc];
    }
    __syncthreads();

    // --- center q into registers (packed f32x2 pairs) ---
    ulonglong2 cq[8];
    {
        const float4* p = sq + ((ty + 3) * 38 + (tx + 3)) * 8;
        int sw = (tx + 3) & 7;
#pragma unroll
        for (int c4 = 0; c4 < 8; c4++) cq[c4] = *(const ulonglong2*)(p + (c4 ^ sw));
    }

    // --- 49 scores ---
    float s[49];
    float smax = -1e30f;
#pragma unroll
    for (int di = 0; di < 7; di++) {
#pragma unroll
        for (int dj = 0; dj < 7; dj++) {
            const float4* np = sq + ((ty + di) * 38 + (tx + dj)) * 8;
            int sw2 = (tx + dj) & 7;
            unsigned long long a0 = 0ull, a1 = 0ull;
#pragma unroll
            for (int c4 = 0; c4 < 8; c4++) {
                ulonglong2 v = *(const ulonglong2*)(np + (c4 ^ sw2));
                fma2(a0, cq[c4].x, v.x);
                fma2(a1, cq[c4].y, v.y);
            }
            float2 f0 = unpack2(a0), f1 = unpack2(a1);
            float sv = (f0.x + f0.y) + (f1.x + f1.y);
            s[di * 7 + dj] = sv;
            smax = fmaxf(smax, sv);
        }
    }

    // --- softmax * spatial, fused normalization ---
    float t = fminf(fmaxf(__expf(temps[stage]), 1e-4f), 1e4f);
    float sig = sigmas[stage];
    float inv2s2 = 1.f / (2.f * sig * sig);
    float Z1 = 0.f, Z2 = 0.f;
#pragma unroll
    for (int di = 0; di < 7; di++) {
        float gy = (float)(di - 3) * (1.f / 3.f);
#pragma unroll
        for (int dj = 0; dj < 7; dj++) {
            float gx = (float)(dj - 3) * (1.f / 3.f);
            float e = __expf(t * (s[di * 7 + dj] - smax));
            float sp = __expf(-(gy * gy + gx * gx) * inv2s2);
            float w = e * sp;
            Z1 += e;
            Z2 += w;
            s[di * 7 + dj] = w;
        }
    }
    float invZ = 1.f / fmaxf(Z2, 1e-7f * Z1);

    // --- adaptive conv over 3 channels ---
    float o0 = 0.f, o1 = 0.f, o2 = 0.f;
#pragma unroll
    for (int di = 0; di < 7; di++) {
#pragma unroll
        for (int dj = 0; dj < 7; dj++) {
            float k = s[di * 7 + dj];
            int off = (ty + di) * 38 + (tx + dj);
            o0 += k * shr[off];
            o1 += k * shr[14 * 38 + off];
            o2 += k * shr[2 * 14 * 38 + off];
        }
    }
    int hw = (blockIdx.y * 8 + ty) * WW + blockIdx.x * 32 + tx;
    float* dst = (stage == 3) ? finalOut : g_hr[srcSel ^ 1];
    dst[(b * 3 + 0) * HH * WW + hw] = o0 * invZ;
    dst[(b * 3 + 1) * HH * WW + hw] = o1 * invZ;
    dst[(b * 3 + 2) * HH * WW + hw] = o2 * invZ;
}

// ---------------- launcher ----------------
extern "C" void kernel_launch(void* const* d_in, const int* in_sizes, int n_in, void* d_out,
                              int out_size) {
    const float* x        = (const float*)d_in[0];
    const float* guidance = (const float*)d_in[1];
    const float* linear_w = (const float*)d_in[2];
    const float* linear_b = (const float*)d_in[3];
    const float* w1s      = (const float*)d_in[4];
    const float* b1s      = (const float*)d_in[5];
    const float* w2s      = (const float*)d_in[6];
    const float* b2s      = (const float*)d_in[7];
    const float* temps    = (const float*)d_in[8];
    const float* sigmas   = (const float*)d_in[9];
    float* out = (float*)d_out;

    cudaFuncSetAttribute(jbu_kernel, cudaFuncAttributeMaxDynamicSharedMemorySize, SMEM_JBU);

    linear_kernel<<<972, 256>>>(x, linear_w, linear_b);
    bicubic_kernel<<<4704, 256>>>();
    for (int st = 0; st < 4; st++) {
        qproj_kernel<<<1568, 256>>>(guidance, w1s + 96 * st, b1s + 32 * st, w2s + 1024 * st,
                                    b2s + 32 * st);
        jbu_kernel<<<dim3(7, 28, NB), dim3(32, 8), SMEM_JBU>>>(temps, sigmas, st, st & 1, out);
    }
}

// round 3
// speedup vs baseline: 1.7796x; 1.7796x over previous
#include <cuda_runtime.h>
#include <cuda_fp16.h>
#include <math.h>

#define HH 224
#define WW 224
#define NB 8
#define CQ 32

// ---------------- scratch (static device globals; no allocation) ----------------
__device__ __half g_qh[4 * NB * HH * WW * CQ];   // [st][b][h][w][c] fp16, ~102.8 MB
__device__ float g_hr[2][NB * 3 * HH * WW];      // ping-pong hr ~9.6 MB
__device__ float g_src[NB * 972];                // linear output = [8][3][18][18]

// ---------------- helpers ----------------
__device__ __forceinline__ void fma2(unsigned long long &acc, unsigned long long a,
                                     unsigned long long b) {
    asm("fma.rn.f32x2 %0, %1, %2, %0;" : "+l"(acc) : "l"(a), "l"(b));
}
__device__ __forceinline__ unsigned long long pack2(float lo, float hi) {
    unsigned long long r;
    asm("mov.b64 %0, {%1,%2};" : "=l"(r) : "f"(lo), "f"(hi));
    return r;
}
__device__ __forceinline__ float2 unpack2(unsigned long long v) {
    float2 f;
    asm("mov.b64 {%0,%1}, %2;" : "=f"(f.x), "=f"(f.y) : "l"(v));
    return f;
}
__device__ __forceinline__ int refl(int i, int n) {
    if (i < 0) i = -i;
    if (i >= n) i = 2 * n - 2 - i;
    return i;
}
__device__ __forceinline__ float cubicw(float d) {
    d = fabsf(d);
    float d2 = d * d, d3 = d2 * d;
    if (d <= 1.f) return 1.25f * d3 - 2.25f * d2 + 1.f;
    if (d < 2.f) return -0.75f * d3 + 3.75f * d2 - 6.f * d + 3.f;
    return 0.f;
}

// ---------------- kernel 1: linear [8,1000] @ [1000,972]^T + b ----------------
__global__ void linear_kernel(const float* __restrict__ x, const float* __restrict__ Wl,
                              const float* __restrict__ bl) {
    int wid = (blockIdx.x * blockDim.x + threadIdx.x) >> 5;
    int lane = threadIdx.x & 31;
    if (wid >= NB * 972) return;
    int b = wid / 972, j = wid % 972;
    const float* xr = x + b * 1000;
    const float* wr = Wl + j * 1000;
    float acc = 0.f;
    for (int c = lane; c < 1000; c += 32) acc += xr[c] * wr[c];
#pragma unroll
    for (int o = 16; o > 0; o >>= 1) acc += __shfl_down_sync(0xffffffffu, acc, o);
    if (lane == 0) g_src[wid] = acc + bl[j];
}

// ---------------- kernel 2: bicubic 18x18 -> 224x224 ----------------
__global__ void bicubic_kernel() {
    int idx = blockIdx.x * blockDim.x + threadIdx.x;
    if (idx >= NB * 3 * HH * WW) return;
    int w = idx % WW;
    int h = (idx / WW) % HH;
    int bc = idx / (HH * WW);

    const float scale = 18.f / 224.f;
    float xi = (w + 0.5f) * scale - 0.5f;
    int x0 = (int)floorf(xi);
    float tx = xi - (float)x0;
    float wx[4];
    int ix[4];
#pragma unroll
    for (int k = 0; k < 4; k++) {
        wx[k] = cubicw(tx - (float)(k - 1));
        int ii = x0 + k - 1;
        ix[k] = ii < 0 ? 0 : (ii > 17 ? 17 : ii);
    }
    float yi = (h + 0.5f) * scale - 0.5f;
    int y0 = (int)floorf(yi);
    float ty = yi - (float)y0;
    float wy[4];
    int iy[4];
#pragma unroll
    for (int k = 0; k < 4; k++) {
        wy[k] = cubicw(ty - (float)(k - 1));
        int ii = y0 + k - 1;
        iy[k] = ii < 0 ? 0 : (ii > 17 ? 17 : ii);
    }
    const float* s = g_src + bc * 324;
    float acc = 0.f;
#pragma unroll
    for (int ky = 0; ky < 4; ky++) {
        float rowacc = 0.f;
#pragma unroll
        for (int kx = 0; kx < 4; kx++) rowacc += wx[kx] * s[iy[ky] * 18 + ix[kx]];
        acc += wy[ky] * rowacc;
    }
    g_hr[0][idx] = acc;
}

// ------- kernel 3: range projection, all 4 stages, fp16 output [pix][32] -------
__global__ void qproj_kernel(const float* __restrict__ guid, const float* __restrict__ w1s,
                             const float* __restrict__ b1s, const float* __restrict__ w2s,
                             const float* __restrict__ b2s) {
    int st = blockIdx.y;
    const float* w1 = w1s + 96 * st;
    const float* b1 = b1s + 32 * st;
    const float* w2 = w2s + 1024 * st;
    const float* b2 = b2s + 32 * st;

    __shared__ float s_w1[96];
    __shared__ float s_b1[32];
    __shared__ float s_b2[32];
    __shared__ unsigned long long s_w2p[512];  // [j2][k] packed pair
    __shared__ unsigned s_out[256][17];        // half2 per 2 channels, padded

    int tid = threadIdx.x;
    if (tid < 96) s_w1[tid] = w1[tid];
    if (tid < 32) {
        s_b1[tid] = b1[tid];
        s_b2[tid] = b2[tid];
    }
    for (int i = tid; i < 512; i += 256) {
        int j2 = i >> 5, k = i & 31;
        s_w2p[i] = pack2(w2[(2 * j2) * 32 + k], w2[(2 * j2 + 1) * 32 + k]);
    }
    __syncthreads();

    int pix = blockIdx.x * 256 + tid;  // exactly covers 8*224*224
    int b = pix / (HH * WW);
    int hw = pix % (HH * WW);
    float g0 = guid[(b * 3 + 0) * HH * WW + hw];
    float g1 = guid[(b * 3 + 1) * HH * WW + hw];
    float g2 = guid[(b * 3 + 2) * HH * WW + hw];

    unsigned long long acc[16];
#pragma unroll
    for (int j2 = 0; j2 < 16; j2++) acc[j2] = pack2(s_b2[2 * j2], s_b2[2 * j2 + 1]);

#pragma unroll
    for (int k = 0; k < 32; k++) {
        float v = s_b1[k] + s_w1[k * 3] * g0 + s_w1[k * 3 + 1] * g1 + s_w1[k * 3 + 2] * g2;
        float h = 0.5f * v * (1.f + erff(v * 0.70710678118654752f));
        unsigned long long hh = pack2(h, h);
#pragma unroll
        for (int j2 = 0; j2 < 16; j2++) fma2(acc[j2], hh, s_w2p[j2 * 32 + k]);
    }
#pragma unroll
    for (int j2 = 0; j2 < 16; j2++) {
        float2 f = unpack2(acc[j2]);
        __half2 h = __floats2half2_rn(f.x, f.y);
        s_out[tid][j2] = *reinterpret_cast<unsigned*>(&h);
    }
    __syncthreads();
    // coalesced fp16 write: 16 half2 (=uint) per pixel
    unsigned* dst = reinterpret_cast<unsigned*>(g_qh) + (size_t)st * (NB * HH * WW * 16) +
                    (size_t)blockIdx.x * 256 * 16;
#pragma unroll
    for (int i = 0; i < 16; i++) {
        int idx = i * 256 + tid;
        dst[idx] = s_out[idx >> 4][idx & 15];
    }
}

// ---- kernel 4: JBU, fused scores+softmax+spatial+adaptive conv, fp16 q ----
#define TQ4 (4 * 14 * 38)                          // float4 count of q tile
#define SMEM_JBU (TQ4 * 16 + 3 * 14 * 38 * 4)      // 34048 + 6384 = 40432 B

__global__ void __launch_bounds__(256, 3)
jbu_kernel(const float* __restrict__ temps, const float* __restrict__ sigmas, int stage,
           int srcSel, float* __restrict__ finalOut) {
    extern __shared__ float smem[];
    float4* sq = (float4*)smem;          // [c4][14][38], 16B elems, lane-stride 16B
    float* shr = smem + TQ4 * 4;         // [3][14][38]

    int tx = threadIdx.x, ty = threadIdx.y;
    int tid = ty * 32 + tx;
    int b = blockIdx.z;
    int gx0 = blockIdx.x * 32 - 3;
    int gy0 = blockIdx.y * 8 - 3;

    // --- load q tile (reflect-padded), chunk-major, conflict-free ---
    const float4* qsrc = reinterpret_cast<const float4*>(
        g_qh + (size_t)stage * (NB * HH * WW * CQ) + (size_t)b * (HH * WW * CQ));
    for (int idx = tid; idx < TQ4; idx += 256) {
        int c4 = idx & 3;
        int col = (idx >> 2) % 38;
        int r = idx / (4 * 38);
        int gr = refl(gy0 + r, HH);
        int gc = refl(gx0 + col, WW);
        sq[(c4 * 14 + r) * 38 + col] = qsrc[(gr * WW + gc) * 4 + c4];
    }
    // --- load hr tile (reflect-padded) ---
    const float* hsrc = g_hr[srcSel] + b * 3 * HH * WW;
    for (int idx = tid; idx < 3 * 14 * 38; idx += 256) {
        int col = idx % 38;
        int r = (idx / 38) % 14;
        int c = idx / (38 * 14);
        int gr = refl(gy0 + r, HH);
        int gc = refl(gx0 + col, WW);
        shr[(c * 14 + r) * 38 + col] = hsrc[c * HH * WW + gr * WW + gc];
    }
    __syncthreads();

    // --- center q into registers as 16 half2 ---
    __half2 cq[16];
#pragma unroll
    for (int c4 = 0; c4 < 4; c4++) {
        float4 v = sq[(c4 * 14 + ty + 3) * 38 + (tx + 3)];
        const __half2* hv = reinterpret_cast<const __half2*>(&v);
        cq[c4 * 4 + 0] = hv[0];
        cq[c4 * 4 + 1] = hv[1];
        cq[c4 * 4 + 2] = hv[2];
        cq[c4 * 4 + 3] = hv[3];
    }

    float t = fminf(fmaxf(__expf(temps[stage]), 1e-4f), 1e4f);
    float tl2e = t * 1.44269504088896f;  // t * log2(e)
    float sig = sigmas[stage];
    // spatial = exp(-(r2/9)/(2 sig^2)) -> exp2(r2 * m2)
    float m2 = -(1.f / (2.f * sig * sig)) * (1.44269504088896f / 9.f);

    float o0 = 0.f, o1 = 0.f, o2 = 0.f, Z1 = 0.f, Z2 = 0.f;
    const __half2 hz = __floats2half2_rn(0.f, 0.f);

#pragma unroll
    for (int di = 0; di < 7; di++) {
#pragma unroll
        for (int dj = 0; dj < 7; dj++) {
            int off = (ty + di) * 38 + (tx + dj);
            __half2 a0 = hz, a1 = hz, a2 = hz, a3 = hz;
#pragma unroll
            for (int c4 = 0; c4 < 4; c4++) {
                float4 v = sq[c4 * 14 * 38 + off];
                const __half2* hv = reinterpret_cast<const __half2*>(&v);
                a0 = __hfma2(cq[c4 * 4 + 0], hv[0], a0);
                a1 = __hfma2(cq[c4 * 4 + 1], hv[1], a1);
                a2 = __hfma2(cq[c4 * 4 + 2], hv[2], a2);
                a3 = __hfma2(cq[c4 * 4 + 3], hv[3], a3);
            }
            __half2 hs = __hadd2(__hadd2(a0, a1), __hadd2(a2, a3));
            float2 fs = __half22float2(hs);
            float s = fs.x + fs.y;
            float se = s * tl2e;
            float r2 = (float)((di - 3) * (di - 3) + (dj - 3) * (dj - 3));
            float e = exp2f(se);            // range term (for Z1 clip)
            float w = exp2f(se + r2 * m2);  // range * spatial
            Z1 += e;
            Z2 += w;
            o0 += w * shr[off];
            o1 += w * shr[532 + off];
            o2 += w * shr[1064 + off];
        }
    }
    float invZ = 1.f / fmaxf(Z2, 1e-7f * Z1);

    int hw = (blockIdx.y * 8 + ty) * WW + blockIdx.x * 32 + tx;
    float* dst = (stage == 3) ? finalOut : g_hr[srcSel ^ 1];
    dst[(b * 3 + 0) * HH * WW + hw] = o0 * invZ;
    dst[(b * 3 + 1) * HH * WW + hw] = o1 * invZ;
    dst[(b * 3 + 2) * HH * WW + hw] = o2 * invZ;
}

// ---------------- launcher ----------------
extern "C" void kernel_launch(void* const* d_in, const int* in_sizes, int n_in, void* d_out,
                              int out_size) {
    const float* x        = (const float*)d_in[0];
    const float* guidance = (const float*)d_in[1];
    const float* linear_w = (const float*)d_in[2];
    const float* linear_b = (const float*)d_in[3];
    const float* w1s      = (const float*)d_in[4];
    const float* b1s      = (const float*)d_in[5];
    const float* w2s      = (const float*)d_in[6];
    const float* b2s      = (const float*)d_in[7];
    const float* temps    = (const float*)d_in[8];
    const float* sigmas   = (const float*)d_in[9];
    float* out = (float*)d_out;

    cudaFuncSetAttribute(jbu_kernel, cudaFuncAttributeMaxDynamicSharedMemorySize, SMEM_JBU);

    linear_kernel<<<972, 256>>>(x, linear_w, linear_b);
    qproj_kernel<<<dim3(1568, 4), 256>>>(guidance, w1s, b1s, w2s, b2s);
    bicubic_kernel<<<4704, 256>>>();
    for (int st = 0; st < 4; st++) {
        jbu_kernel<<<dim3(7, 28, NB), dim3(32, 8), SMEM_JBU>>>(temps, sigmas, st, st & 1, out);
    }
}

// round 5
// speedup vs baseline: 1.8587x; 1.0445x over previous
#include <cuda_runtime.h>
#include <cuda_fp16.h>
#include <math.h>

#define HH 224
#define WW 224
#define NB 8
#define CQ 32

// ---------------- scratch (static device globals; no allocation) ----------------
__device__ __half g_qh[4 * NB * HH * WW * CQ];   // [st][b][h][w][c] fp16
__device__ float g_hr[2][NB * 3 * HH * WW];      // ping-pong hr
__device__ float g_src[NB * 972];                // linear output = [8][3][18][18]

// ---------------- helpers ----------------
__device__ __forceinline__ void fma2(unsigned long long &acc, unsigned long long a,
                                     unsigned long long b) {
    asm("fma.rn.f32x2 %0, %1, %2, %0;" : "+l"(acc) : "l"(a), "l"(b));
}
__device__ __forceinline__ unsigned long long pack2(float lo, float hi) {
    unsigned long long r;
    asm("mov.b64 %0, {%1,%2};" : "=l"(r) : "f"(lo), "f"(hi));
    return r;
}
__device__ __forceinline__ float2 unpack2(unsigned long long v) {
    float2 f;
    asm("mov.b64 {%0,%1}, %2;" : "=f"(f.x), "=f"(f.y) : "l"(v));
    return f;
}
__device__ __forceinline__ float htanh(float x) {
    float r;
    asm("tanh.approx.f32 %0, %1;" : "=f"(r) : "f"(x));
    return r;
}
__device__ __forceinline__ int refl(int i, int n) {
    if (i < 0) i = -i;
    if (i >= n) i = 2 * n - 2 - i;
    return i;
}
__device__ __forceinline__ float cubicw(float d) {
    d = fabsf(d);
    float d2 = d * d, d3 = d2 * d;
    if (d <= 1.f) return 1.25f * d3 - 2.25f * d2 + 1.f;
    if (d < 2.f) return -0.75f * d3 + 3.75f * d2 - 6.f * d + 3.f;
    return 0.f;
}

// ---------------- kernel 1: linear [8,1000] @ [1000,972]^T + b ----------------
__global__ void linear_kernel(const float* __restrict__ x, const float* __restrict__ Wl,
                              const float* __restrict__ bl) {
    int wid = (blockIdx.x * blockDim.x + threadIdx.x) >> 5;
    int lane = threadIdx.x & 31;
    if (wid >= NB * 972) return;
    int b = wid / 972, j = wid % 972;
    const float* xr = x + b * 1000;
    const float* wr = Wl + j * 1000;
    float acc = 0.f;
    for (int c = lane; c < 1000; c += 32) acc += xr[c] * wr[c];
#pragma unroll
    for (int o = 16; o > 0; o >>= 1) acc += __shfl_down_sync(0xffffffffu, acc, o);
    if (lane == 0) g_src[wid] = acc + bl[j];
}

// ---------------- kernel 2: bicubic 18x18 -> 224x224 ----------------
__global__ void bicubic_kernel() {
    int idx = blockIdx.x * blockDim.x + threadIdx.x;
    if (idx >= NB * 3 * HH * WW) return;
    int w = idx % WW;
    int h = (idx / WW) % HH;
    int bc = idx / (HH * WW);

    const float scale = 18.f / 224.f;
    float xi = (w + 0.5f) * scale - 0.5f;
    int x0 = (int)floorf(xi);
    float tx = xi - (float)x0;
    float wx[4];
    int ix[4];
#pragma unroll
    for (int k = 0; k < 4; k++) {
        wx[k] = cubicw(tx - (float)(k - 1));
        int ii = x0 + k - 1;
        ix[k] = ii < 0 ? 0 : (ii > 17 ? 17 : ii);
    }
    float yi = (h + 0.5f) * scale - 0.5f;
    int y0 = (int)floorf(yi);
    float ty = yi - (float)y0;
    float wy[4];
    int iy[4];
#pragma unroll
    for (int k = 0; k < 4; k++) {
        wy[k] = cubicw(ty - (float)(k - 1));
        int ii = y0 + k - 1;
        iy[k] = ii < 0 ? 0 : (ii > 17 ? 17 : ii);
    }
    const float* s = g_src + bc * 324;
    float acc = 0.f;
#pragma unroll
    for (int ky = 0; ky < 4; ky++) {
        float rowacc = 0.f;
#pragma unroll
        for (int kx = 0; kx < 4; kx++) rowacc += wx[kx] * s[iy[ky] * 18 + ix[kx]];
        acc += wy[ky] * rowacc;
    }
    g_hr[0][idx] = acc;
}

// ------- kernel 3: range projection, all 4 stages, fp16 output [pix][32] -------
__global__ void qproj_kernel(const float* __restrict__ guid, const float* __restrict__ w1s,
                             const float* __restrict__ b1s, const float* __restrict__ w2s,
                             const float* __restrict__ b2s) {
    int st = blockIdx.y;
    const float* w1 = w1s + 96 * st;
    const float* b1 = b1s + 32 * st;
    const float* w2 = w2s + 1024 * st;
    const float* b2 = b2s + 32 * st;

    __shared__ float s_w1[96];
    __shared__ float s_b1[32];
    __shared__ float s_b2[32];
    __shared__ unsigned long long s_w2p[512];  // [j2][k] packed pair
    __shared__ unsigned s_out[256][17];        // half2 per 2 channels, padded

    int tid = threadIdx.x;
    if (tid < 96) s_w1[tid] = w1[tid];
    if (tid < 32) {
        s_b1[tid] = b1[tid];
        s_b2[tid] = b2[tid];
    }
    for (int i = tid; i < 512; i += 256) {
        int j2 = i >> 5, k = i & 31;
        s_w2p[i] = pack2(w2[(2 * j2) * 32 + k], w2[(2 * j2 + 1) * 32 + k]);
    }
    __syncthreads();

    int pix = blockIdx.x * 256 + tid;  // exactly covers 8*224*224
    int b = pix / (HH * WW);
    int hw = pix % (HH * WW);
    float g0 = guid[(b * 3 + 0) * HH * WW + hw];
    float g1 = guid[(b * 3 + 1) * HH * WW + hw];
    float g2 = guid[(b * 3 + 2) * HH * WW + hw];

    unsigned long long acc[16];
#pragma unroll
    for (int j2 = 0; j2 < 16; j2++) acc[j2] = pack2(s_b2[2 * j2], s_b2[2 * j2 + 1]);

#pragma unroll
    for (int k = 0; k < 32; k++) {
        float v = s_b1[k] + s_w1[k * 3] * g0 + s_w1[k * 3 + 1] * g1 + s_w1[k * 3 + 2] * g2;
        // tanh-approx gelu (HW tanh); |v| is tiny here so deviation is negligible
        float u = 0.7978845608f * v * (1.f + 0.044715f * v * v);
        float h = 0.5f * v * (1.f + htanh(u));
        unsigned long long hh = pack2(h, h);
#pragma unroll
        for (int j2 = 0; j2 < 16; j2++) fma2(acc[j2], hh, s_w2p[j2 * 32 + k]);
    }
#pragma unroll
    for (int j2 = 0; j2 < 16; j2++) {
        float2 f = unpack2(acc[j2]);
        __half2 h = __floats2half2_rn(f.x, f.y);
        s_out[tid][j2] = *reinterpret_cast<unsigned*>(&h);
    }
    __syncthreads();
    unsigned* dst = reinterpret_cast<unsigned*>(g_qh) + (size_t)st * (NB * HH * WW * 16) +
                    (size_t)blockIdx.x * 256 * 16;
#pragma unroll
    for (int i = 0; i < 16; i++) {
        int idx = i * 256 + tid;
        dst[idx] = s_out[idx >> 4][idx & 15];
    }
}

// ---- kernel 4: JBU, 2 vertical pixels per thread ----
#define TQ4 (4 * 14 * 38)                               // float4 count of q tile
#define SMEM_JBU (TQ4 * 16 + 3 * 14 * 38 * 4 + 49 * 4)  // 34048 + 6384 + 196

struct TapState {
    float o0, o1, o2, Z1, Z2;
};

template <bool DA, bool DB>
__device__ __forceinline__ void tap_body(const float4* __restrict__ sq,
                                         const float* __restrict__ shr,
                                         const float* __restrict__ ssp, int off, int spa,
                                         int spb, const __half2* cqa, const __half2* cqb,
                                         float tl2e, TapState& A, TapState& B) {
    __half2 hv[16];
#pragma unroll
    for (int c4 = 0; c4 < 4; c4++) {
        float4 v = sq[c4 * 532 + off];
        const __half2* p = reinterpret_cast<const __half2*>(&v);
        hv[c4 * 4 + 0] = p[0];
        hv[c4 * 4 + 1] = p[1];
        hv[c4 * 4 + 2] = p[2];
        hv[c4 * 4 + 3] = p[3];
    }
    float h0 = shr[off], h1 = shr[532 + off], h2 = shr[1064 + off];
    const __half2 hz = __floats2half2_rn(0.f, 0.f);
    if (DA) {
        __half2 a0 = hz, a1 = hz, a2 = hz, a3 = hz;
#pragma unroll
        for (int c4 = 0; c4 < 4; c4++) {
            a0 = __hfma2(cqa[c4 * 4 + 0], hv[c4 * 4 + 0], a0);
            a1 = __hfma2(cqa[c4 * 4 + 1], hv[c4 * 4 + 1], a1);
            a2 = __hfma2(cqa[c4 * 4 + 2], hv[c4 * 4 + 2], a2);
            a3 = __hfma2(cqa[c4 * 4 + 3], hv[c4 * 4 + 3], a3);
        }
        float2 fs = __half22float2(__hadd2(__hadd2(a0, a1), __hadd2(a2, a3)));
        float e = exp2f((fs.x + fs.y) * tl2e);
        float w = e * ssp[spa];
        A.Z1 += e;
        A.Z2 += w;
        A.o0 += w * h0;
        A.o1 += w * h1;
        A.o2 += w * h2;
    }
    if (DB) {
        __half2 a0 = hz, a1 = hz, a2 = hz, a3 = hz;
#pragma unroll
        for (int c4 = 0; c4 < 4; c4++) {
            a0 = __hfma2(cqb[c4 * 4 + 0], hv[c4 * 4 + 0], a0);
            a1 = __hfma2(cqb[c4 * 4 + 1], hv[c4 * 4 + 1], a1);
            a2 = __hfma2(cqb[c4 * 4 + 2], hv[c4 * 4 + 2], a2);
            a3 = __hfma2(cqb[c4 * 4 + 3], hv[c4 * 4 + 3], a3);
        }
        float2 fs = __half22float2(__hadd2(__hadd2(a0, a1), __hadd2(a2, a3)));
        float e = exp2f((fs.x + fs.y) * tl2e);
        float w = e * ssp[spb];
        B.Z1 += e;
        B.Z2 += w;
        B.o0 += w * h0;
        B.o1 += w * h1;
        B.o2 += w * h2;
    }
}

__global__ void __launch_bounds__(128, 4)
jbu_kernel(const float* __restrict__ temps, const float* __restrict__ sigmas, int stage,
           int srcSel, float* __restrict__ finalOut) {
    extern __shared__ float smem[];
    float4* sq = (float4*)smem;              // [c4][14][38], 16B elems
    float* shr = smem + TQ4 * 4;             // [3][14][38]
    float* ssp = shr + 3 * 14 * 38;          // [49] spatial table

    int tx = threadIdx.x, ty = threadIdx.y;  // 32 x 4
    int tid = ty * 32 + tx;
    int b = blockIdx.z;
    int gx0 = blockIdx.x * 32 - 3;
    int gy0 = blockIdx.y * 8 - 3;

    if (tid < 49) {
        float sig = sigmas[stage];
        float m2 = -(1.f / (2.f * sig * sig)) * (1.44269504088896f / 9.f);
        int di = tid / 7 - 3, dj = tid % 7 - 3;
        ssp[tid] = exp2f((float)(di * di + dj * dj) * m2);
    }

    // --- load q tile (reflect-padded), chunk-major, conflict-free ---
    const float4* qsrc = reinterpret_cast<const float4*>(
        g_qh + (size_t)stage * (NB * HH * WW * CQ) + (size_t)b * (HH * WW * CQ));
    for (int idx = tid; idx < TQ4; idx += 128) {
        int c4 = idx & 3;
        int col = (idx >> 2) % 38;
        int r = idx / (4 * 38);
        int gr = refl(gy0 + r, HH);
        int gc = refl(gx0 + col, WW);
        sq[(c4 * 14 + r) * 38 + col] = qsrc[(gr * WW + gc) * 4 + c4];
    }
    // --- load hr tile (reflect-padded) ---
    const float* hsrc = g_hr[srcSel] + b * 3 * HH * WW;
    for (int idx = tid; idx < 3 * 14 * 38; idx += 128) {
        int col = idx % 38;
        int r = (idx / 38) % 14;
        int c = idx / (38 * 14);
        int gr = refl(gy0 + r, HH);
        int gc = refl(gx0 + col, WW);
        shr[(c * 14 + r) * 38 + col] = hsrc[c * HH * WW + gr * WW + gc];
    }
    __syncthreads();

    // --- two center q vectors (rows 2ty, 2ty+1) ---
    __half2 cqa[16], cqb[16];
#pragma unroll
    for (int c4 = 0; c4 < 4; c4++) {
        float4 va = sq[(c4 * 14 + 2 * ty + 3) * 38 + (tx + 3)];
        float4 vb = sq[(c4 * 14 + 2 * ty + 4) * 38 + (tx + 3)];
        const __half2* pa = reinterpret_cast<const __half2*>(&va);
        const __half2* pb = reinterpret_cast<const __half2*>(&vb);
#pragma unroll
        for (int k = 0; k < 4; k++) {
            cqa[c4 * 4 + k] = pa[k];
            cqb[c4 * 4 + k] = pb[k];
        }
    }

    float t = fminf(fmaxf(__expf(temps[stage]), 1e-4f), 1e4f);
    float tl2e = t * 1.44269504088896f;

    TapState A = {0.f, 0.f, 0.f, 0.f, 0.f};
    TapState B = {0.f, 0.f, 0.f, 0.f, 0.f};

    // rr = row offset + 3 relative to pixel a; tile row = 2ty + rr
    // pixel a valid rr 0..6, pixel b valid rr 1..7
#pragma unroll
    for (int dj = 0; dj < 7; dj++) {
        int off = (2 * ty + 0) * 38 + tx + dj;
        tap_body<true, false>(sq, shr, ssp, off, 0 * 7 + dj, 0, cqa, cqb, tl2e, A, B);
    }
#pragma unroll
    for (int rr = 1; rr <= 6; rr++) {
#pragma unroll
        for (int dj = 0; dj < 7; dj++) {
            int off = (2 * ty + rr) * 38 + tx + dj;
            tap_body<true, true>(sq, shr, ssp, off, rr * 7 + dj, (rr - 1) * 7 + dj, cqa, cqb,
                                 tl2e, A, B);
        }
    }
#pragma unroll
    for (int dj = 0; dj < 7; dj++) {
        int off = (2 * ty + 7) * 38 + tx + dj;
        tap_body<false, true>(sq, shr, ssp, off, 0, 6 * 7 + dj, cqa, cqb, tl2e, A, B);
    }

    float invZa = 1.f / fmaxf(A.Z2, 1e-7f * A.Z1);
    float invZb = 1.f / fmaxf(B.Z2, 1e-7f * B.Z1);

    int pya = blockIdx.y * 8 + 2 * ty;
    int px = blockIdx.x * 32 + tx;
    float* dst = (stage == 3) ? finalOut : g_hr[srcSel ^ 1];
    float* d0 = dst + (b * 3 + 0) * HH * WW;
    float* d1 = dst + (b * 3 + 1) * HH * WW;
    float* d2 = dst + (b * 3 + 2) * HH * WW;
    d0[pya * WW + px] = A.o0 * invZa;
    d1[pya * WW + px] = A.o1 * invZa;
    d2[pya * WW + px] = A.o2 * invZa;
    d0[(pya + 1) * WW + px] = B.o0 * invZb;
    d1[(pya + 1) * WW + px] = B.o1 * invZb;
    d2[(pya + 1) * WW + px] = B.o2 * invZb;
}

// ---------------- launcher ----------------
extern "C" void kernel_launch(void* const* d_in, const int* in_sizes, int n_in, void* d_out,
                              int out_size) {
    const float* x        = (const float*)d_in[0];
    const float* guidance = (const float*)d_in[1];
    const float* linear_w = (const float*)d_in[2];
    const float* linear_b = (const float*)d_in[3];
    const float* w1s      = (const float*)d_in[4];
    const float* b1s      = (const float*)d_in[5];
    const float* w2s      = (const float*)d_in[6];
    const float* b2s      = (const float*)d_in[7];
    const float* temps    = (const float*)d_in[8];
    const float* sigmas   = (const float*)d_in[9];
    float* out = (float*)d_out;

    cudaFuncSetAttribute(jbu_kernel, cudaFuncAttributeMaxDynamicSharedMemorySize, SMEM_JBU);

    linear_kernel<<<972, 256>>>(x, linear_w, linear_b);
    qproj_kernel<<<dim3(1568, 4), 256>>>(guidance, w1s, b1s, w2s, b2s);
    bicubic_kernel<<<4704, 256>>>();
    for (int st = 0; st < 4; st++) {
        jbu_kernel<<<dim3(7, 28, NB), dim3(32, 4), SMEM_JBU>>>(temps, sigmas, st, st & 1, out);
    }
}

// round 7
// speedup vs baseline: 2.5719x; 1.3837x over previous
#include <cuda_runtime.h>
#include <cuda_bf16.h>
#include <cstdint>
#include <math.h>

#define HH 224
#define WW 224
#define NB 8
#define CQ 32
#define HW (HH * WW)

// ---------------- scratch (static device globals; no allocation) ----------------
__device__ __nv_bfloat16 g_qb[4 * NB * HW * CQ];  // [st][b][h][w][c] bf16
__device__ float g_hr[2][NB * 3 * HW];            // ping-pong hr
__device__ float g_src[NB * 972];                 // linear output

// ---------------- generic helpers ----------------
__device__ __forceinline__ void fma2(unsigned long long& acc, unsigned long long a,
                                     unsigned long long b) {
    asm("fma.rn.f32x2 %0, %1, %2, %0;" : "+l"(acc) : "l"(a), "l"(b));
}
__device__ __forceinline__ unsigned long long pack2(float lo, float hi) {
    unsigned long long r;
    asm("mov.b64 %0, {%1,%2};" : "=l"(r) : "f"(lo), "f"(hi));
    return r;
}
__device__ __forceinline__ float2 unpack2(unsigned long long v) {
    float2 f;
    asm("mov.b64 {%0,%1}, %2;" : "=f"(f.x), "=f"(f.y) : "l"(v));
    return f;
}
__device__ __forceinline__ float htanh(float x) {
    float r;
    asm("tanh.approx.f32 %0, %1;" : "=f"(r) : "f"(x));
    return r;
}
__device__ __forceinline__ uint32_t smem_u32(const void* p) {
    uint32_t a;
    asm("{ .reg .u64 t; cvta.to.shared.u64 t, %1; cvt.u32.u64 %0, t; }" : "=r"(a) : "l"(p));
    return a;
}
__device__ __forceinline__ int refl(int i, int n) {
    if (i < 0) i = -i;
    if (i >= n) i = 2 * n - 2 - i;
    return i;
}
__device__ __forceinline__ float cubicw(float d) {
    d = fabsf(d);
    float d2 = d * d, d3 = d2 * d;
    if (d <= 1.f) return 1.25f * d3 - 2.25f * d2 + 1.f;
    if (d < 2.f) return -0.75f * d3 + 3.75f * d2 - 6.f * d + 3.f;
    return 0.f;
}

// ---------------- kernel 1: linear ----------------
__global__ void linear_kernel(const float* __restrict__ x, const float* __restrict__ Wl,
                              const float* __restrict__ bl) {
    int wid = (blockIdx.x * blockDim.x + threadIdx.x) >> 5;
    int lane = threadIdx.x & 31;
    if (wid >= NB * 972) return;
    int b = wid / 972, j = wid % 972;
    const float* xr = x + b * 1000;
    const float* wr = Wl + j * 1000;
    float acc = 0.f;
    for (int c = lane; c < 1000; c += 32) acc += xr[c] * wr[c];
#pragma unroll
    for (int o = 16; o > 0; o >>= 1) acc += __shfl_down_sync(0xffffffffu, acc, o);
    if (lane == 0) g_src[wid] = acc + bl[j];
}

// ---------------- kernel 2: bicubic 18 -> 224 ----------------
__global__ void bicubic_kernel() {
    int idx = blockIdx.x * blockDim.x + threadIdx.x;
    if (idx >= NB * 3 * HW) return;
    int w = idx % WW;
    int h = (idx / WW) % HH;
    int bc = idx / HW;
    const float scale = 18.f / 224.f;
    float xi = (w + 0.5f) * scale - 0.5f;
    int x0 = (int)floorf(xi);
    float tx = xi - (float)x0;
    float wx[4];
    int ix[4];
#pragma unroll
    for (int k = 0; k < 4; k++) {
        wx[k] = cubicw(tx - (float)(k - 1));
        int ii = x0 + k - 1;
        ix[k] = ii < 0 ? 0 : (ii > 17 ? 17 : ii);
    }
    float yi = (h + 0.5f) * scale - 0.5f;
    int y0 = (int)floorf(yi);
    float ty = yi - (float)y0;
    float wy[4];
    int iy[4];
#pragma unroll
    for (int k = 0; k < 4; k++) {
        wy[k] = cubicw(ty - (float)(k - 1));
        int ii = y0 + k - 1;
        iy[k] = ii < 0 ? 0 : (ii > 17 ? 17 : ii);
    }
    const float* s = g_src + bc * 324;
    float acc = 0.f;
#pragma unroll
    for (int ky = 0; ky < 4; ky++) {
        float r = 0.f;
#pragma unroll
        for (int kx = 0; kx < 4; kx++) r += wx[kx] * s[iy[ky] * 18 + ix[kx]];
        acc += wy[ky] * r;
    }
    g_hr[0][idx] = acc;
}

// ------- kernel 3: range projection; layer1 fma + layer2 via mma.sync (HMMA) -------
#define LDM_X4(r0, r1, r2, r3, a)                                              \
    asm volatile("ldmatrix.sync.aligned.m8n8.x4.shared.b16 {%0,%1,%2,%3}, [%4];" \
                 : "=r"(r0), "=r"(r1), "=r"(r2), "=r"(r3) : "r"(a))
#define LDM_X2(r0, r1, a)                                                  \
    asm volatile("ldmatrix.sync.aligned.m8n8.x2.shared.b16 {%0,%1}, [%2];" \
                 : "=r"(r0), "=r"(r1) : "r"(a))
#define MMA_BF16(d, a, b)                                                           \
    asm volatile(                                                                   \
        "mma.sync.aligned.m16n8k16.row.col.f32.bf16.bf16.f32 "                      \
        "{%0,%1,%2,%3}, {%4,%5,%6,%7}, {%8,%9}, {%0,%1,%2,%3};"                     \
        : "+f"((d)[0]), "+f"((d)[1]), "+f"((d)[2]), "+f"((d)[3])                    \
        : "r"((a)[0]), "r"((a)[1]), "r"((a)[2]), "r"((a)[3]), "r"((b)[0]),          \
          "r"((b)[1]))

__global__ void __launch_bounds__(128) qproj_kernel(const float* __restrict__ guid,
                                                    const float* __restrict__ w1s,
                                                    const float* __restrict__ b1s,
                                                    const float* __restrict__ w2s,
                                                    const float* __restrict__ b2s) {
    __shared__ __nv_bfloat16 s_h[128 * 40];   // h staging, row stride 40 (conflict-free LDSM)
    __shared__ __nv_bfloat16 s_w2[32 * 40];   // W2 [j][k]
    __shared__ float s_w1[96], s_b1[32], s_b2[32];

    int st = blockIdx.y;
    int tid = threadIdx.x;
    int lane = tid & 31;
    int wrp = tid >> 5;

    if (tid < 96) s_w1[tid] = w1s[96 * st + tid];
    if (tid < 32) {
        s_b1[tid] = b1s[32 * st + tid];
        s_b2[tid] = b2s[32 * st + tid];
    }
    for (int i = tid; i < 1024; i += 128) {
        int n = i >> 5, k = i & 31;
        s_w2[n * 40 + k] = __float2bfloat16(w2s[1024 * st + n * 32 + k]);
    }

    // ---- layer 1 + gelu for this thread's pixel; stage h as bf16 ----
    int px = blockIdx.x * 128 + tid;  // exact multiple: 401408 = 3136*128
    int b = px / HW, hw = px % HW;
    float g0 = guid[(b * 3 + 0) * HW + hw];
    float g1 = guid[(b * 3 + 1) * HW + hw];
    float g2 = guid[(b * 3 + 2) * HW + hw];
    uint32_t* hrow = reinterpret_cast<uint32_t*>(&s_h[tid * 40]);
#pragma unroll
    for (int k2 = 0; k2 < 16; k2++) {
        float h01[2];
#pragma unroll
        for (int u = 0; u < 2; u++) {
            int k = 2 * k2 + u;
            float v = s_b1[k] + s_w1[k * 3] * g0 + s_w1[k * 3 + 1] * g1 + s_w1[k * 3 + 2] * g2;
            float uu = 0.7978845608f * v * (1.f + 0.044715f * v * v);
            h01[u] = 0.5f * v * (1.f + htanh(uu));
        }
        __nv_bfloat162 p = __floats2bfloat162_rn(h01[0], h01[1]);
        hrow[k2] = *reinterpret_cast<uint32_t*>(&p);
    }
    __syncthreads();

    // ---- B fragments: W2 [n][k], 4 n-tiles x 2 k-steps ----
    uint32_t su_w2 = smem_u32(s_w2);
    int l16 = lane & 15;
    uint32_t bfr[4][2][2];
#pragma unroll
    for (int nt = 0; nt < 4; nt++)
#pragma unroll
        for (int ks = 0; ks < 2; ks++) {
            uint32_t a = su_w2 +
                         ((nt * 8 + (l16 & 7)) * 40 + ks * 16 + ((l16 >> 3) & 1) * 8) * 2;
            LDM_X2(bfr[nt][ks][0], bfr[nt][ks][1], a);
        }

    // ---- A fragments + MMA: warp owns 32 pixels (2 m-tiles) ----
    uint32_t su_h = smem_u32(s_h);
    float d[2][4][4];
#pragma unroll
    for (int mt = 0; mt < 2; mt++)
#pragma unroll
        for (int nt = 0; nt < 4; nt++)
#pragma unroll
            for (int i = 0; i < 4; i++) d[mt][nt][i] = 0.f;

#pragma unroll
    for (int ks = 0; ks < 2; ks++) {
#pragma unroll
        for (int mt = 0; mt < 2; mt++) {
            int row = wrp * 32 + mt * 16 + ((lane >> 3) & 1) * 8 + (lane & 7);
            uint32_t a = su_h + (row * 40 + ks * 16 + (lane >> 4) * 8) * 2;
            uint32_t af[4];
            LDM_X4(af[0], af[1], af[2], af[3], a);
#pragma unroll
            for (int nt = 0; nt < 4; nt++) MMA_BF16(d[mt][nt], af, bfr[nt][ks]);
        }
    }

    // ---- epilogue: + bias, pack bf16x2, store ----
    uint32_t* qdst = reinterpret_cast<uint32_t*>(g_qb + (size_t)st * (NB * HW * CQ));
    int base_px = blockIdx.x * 128 + wrp * 32;
    int row_lo = lane >> 2;
    int col0 = (lane & 3) * 2;
#pragma unroll
    for (int mt = 0; mt < 2; mt++) {
#pragma unroll
        for (int nt = 0; nt < 4; nt++) {
            int ch = nt * 8 + col0;
            float bb0 = s_b2[ch], bb1 = s_b2[ch + 1];
            int p0 = base_px + mt * 16 + row_lo;
            __nv_bfloat162 lo = __floats2bfloat162_rn(d[mt][nt][0] + bb0, d[mt][nt][1] + bb1);
            __nv_bfloat162 hi = __floats2bfloat162_rn(d[mt][nt][2] + bb0, d[mt][nt][3] + bb1);
            qdst[p0 * 16 + ch / 2] = *reinterpret_cast<uint32_t*>(&lo);
            qdst[(p0 + 8) * 16 + ch / 2] = *reinterpret_cast<uint32_t*>(&hi);
        }
    }
}

// ---- kernel 4: JBU, 2 vertical pixels/thread, bf16 dots ----
#define TQ4 (4 * 14 * 38)
#define SMEM_JBU (TQ4 * 16 + 14 * 38 * 16)  // 34048 + 8512 = 42560

struct Px {
    unsigned long long a01, a2z;  // (o0,o1), (o2,Z2)
    float Z1;
};

template <bool NZ1>
__device__ __forceinline__ void do_px(const float4* qv, const float4& hv,
                                      const __nv_bfloat162* cq, float tl2e, float rowterm,
                                      float cdj, float m2, Px& P) {
    __nv_bfloat162 a0, a1, a2, a3;
    {
        const __nv_bfloat162* p0 = reinterpret_cast<const __nv_bfloat162*>(&qv[0]);
        a0 = __hmul2(cq[0], p0[0]);
        a1 = __hmul2(cq[1], p0[1]);
        a2 = __hmul2(cq[2], p0[2]);
        a3 = __hmul2(cq[3], p0[3]);
    }
#pragma unroll
    for (int c4 = 1; c4 < 4; c4++) {
        const __nv_bfloat162* p = reinterpret_cast<const __nv_bfloat162*>(&qv[c4]);
        a0 = __hfma2(cq[c4 * 4 + 0], p[0], a0);
        a1 = __hfma2(cq[c4 * 4 + 1], p[1], a1);
        a2 = __hfma2(cq[c4 * 4 + 2], p[2], a2);
        a3 = __hfma2(cq[c4 * 4 + 3], p[3], a3);
    }
    float2 fs = __bfloat1622float2(__hadd2(__hadd2(a0, a1), __hadd2(a2, a3)));
    float s = fs.x + fs.y;
    float t1 = fmaf(s, tl2e, rowterm);
    float w = exp2f(fmaf(m2, cdj, t1));
    if (NZ1) P.Z1 += exp2f(s * tl2e);
    unsigned long long ww = pack2(w, w);
    fma2(P.a01, ww, pack2(hv.x, hv.y));
    fma2(P.a2z, ww, pack2(hv.z, 1.0f));
}

template <bool NZ1>
__device__ __forceinline__ void jbu_main(const float4* __restrict__ sq,
                                         const float4* __restrict__ shr4, int tx, int ty,
                                         const __nv_bfloat162* cqa, const __nv_bfloat162* cqb,
                                         float tl2e, float m2, Px& A, Px& B) {
    {
        const float4* qb = sq + (2 * ty) * 38 + tx;
        const float4* hb = shr4 + (2 * ty) * 38 + tx;
        float rta = 9.f * m2;
#pragma unroll
        for (int dj = 0; dj < 7; dj++) {
            float4 qv[4] = {qb[dj], qb[532 + dj], qb[1064 + dj], qb[1596 + dj]};
            float4 hv = hb[dj];
            do_px<NZ1>(qv, hv, cqa, tl2e, rta, (float)((dj - 3) * (dj - 3)), m2, A);
        }
    }
#pragma unroll 1
    for (int rr = 1; rr <= 6; rr++) {
        const float4* qb = sq + (2 * ty + rr) * 38 + tx;
        const float4* hb = shr4 + (2 * ty + rr) * 38 + tx;
        int da = rr - 3, db = rr - 4;
        float rta = (float)(da * da) * m2;
        float rtb = (float)(db * db) * m2;
#pragma unroll
        for (int dj = 0; dj < 7; dj++) {
            float4 qv[4] = {qb[dj], qb[532 + dj], qb[1064 + dj], qb[1596 + dj]};
            float4 hv = hb[dj];
            float cdj = (float)((dj - 3) * (dj - 3));
            do_px<NZ1>(qv, hv, cqa, tl2e, rta, cdj, m2, A);
            do_px<NZ1>(qv, hv, cqb, tl2e, rtb, cdj, m2, B);
        }
    }
    {
        const float4* qb = sq + (2 * ty + 7) * 38 + tx;
        const float4* hb = shr4 + (2 * ty + 7) * 38 + tx;
        float rtb = 9.f * m2;
#pragma unroll
        for (int dj = 0; dj < 7; dj++) {
            float4 qv[4] = {qb[dj], qb[532 + dj], qb[1064 + dj], qb[1596 + dj]};
            float4 hv = hb[dj];
            do_px<NZ1>(qv, hv, cqb, tl2e, rtb, (float)((dj - 3) * (dj - 3)), m2, B);
        }
    }
}

__global__ void __launch_bounds__(128, 5)
jbu_kernel(const float* __restrict__ temps, const float* __restrict__ sigmas, int stage,
           int srcSel, float* __restrict__ finalOut) {
    extern __shared__ float smem[];
    float4* sq = (float4*)smem;                // [c4][14][38] bf16x8 chunks
    float4* shr4 = (float4*)(smem + TQ4 * 4);  // [14][38] (h0,h1,h2,1)

    int tx = threadIdx.x, ty = threadIdx.y;  // 32 x 4
    int tid = ty * 32 + tx;
    int b = blockIdx.z;
    int gx0 = blockIdx.x * 32 - 3;
    int gy0 = blockIdx.y * 8 - 3;

    const float4* qsrc = reinterpret_cast<const float4*>(
        g_qb + (size_t)stage * (NB * HW * CQ) + (size_t)b * (HW * CQ));
    for (int idx = tid; idx < 4 * 14 * 38; idx += 128) {
        int c4 = idx & 3;
        int col = (idx >> 2) % 38;
        int r = idx / (4 * 38);
        int gr = refl(gy0 + r, HH);
        int gc = refl(gx0 + col, WW);
        sq[(c4 * 14 + r) * 38 + col] = qsrc[(gr * WW + gc) * 4 + c4];
    }
    const float* hsrc = g_hr[srcSel] + b * 3 * HW;
    for (int idx = tid; idx < 14 * 38; idx += 128) {
        int col = idx % 38;
        int r = idx / 38;
        int gr = refl(gy0 + r, HH);
        int gc = refl(gx0 + col, WW);
        int g = gr * WW + gc;
        shr4[r * 38 + col] = make_float4(hsrc[g], hsrc[HW + g], hsrc[2 * HW + g], 1.0f);
    }
    __syncthreads();

    __nv_bfloat162 cqa[16], cqb[16];
#pragma unroll
    for (int c4 = 0; c4 < 4; c4++) {
        float4 va = sq[(c4 * 14 + 2 * ty + 3) * 38 + (tx + 3)];
        float4 vb = sq[(c4 * 14 + 2 * ty + 4) * 38 + (tx + 3)];
        const __nv_bfloat162* pa = reinterpret_cast<const __nv_bfloat162*>(&va);
        const __nv_bfloat162* pb = reinterpret_cast<const __nv_bfloat162*>(&vb);
#pragma unroll
        for (int k = 0; k < 4; k++) {
            cqa[c4 * 4 + k] = pa[k];
            cqb[c4 * 4 + k] = pb[k];
        }
    }

    float t = fminf(fmaxf(__expf(temps[stage]), 1e-4f), 1e4f);
    float tl2e = t * 1.44269504088896f;
    float sig = sigmas[stage];
    float m2 = -(1.f / (2.f * sig * sig)) * (1.44269504088896f / 9.f);

    Px A = {0ull, 0ull, 0.f}, B = {0ull, 0ull, 0.f};
    bool fast = (exp2f(18.f * m2) >= 1e-7f);  // then Z2 >= 1e-7*Z1 always
    if (fast)
        jbu_main<false>(sq, shr4, tx, ty, cqa, cqb, tl2e, m2, A, B);
    else
        jbu_main<true>(sq, shr4, tx, ty, cqa, cqb, tl2e, m2, A, B);

    float2 a01 = unpack2(A.a01), a2z = unpack2(A.a2z);
    float2 b01 = unpack2(B.a01), b2z = unpack2(B.a2z);
    float invZa = 1.f / (fast ? a2z.y : fmaxf(a2z.y, 1e-7f * A.Z1));
    float invZb = 1.f / (fast ? b2z.y : fmaxf(b2z.y, 1e-7f * B.Z1));

    int pya = blockIdx.y * 8 + 2 * ty;
    int px = blockIdx.x * 32 + tx;
    float* dst = (stage == 3) ? finalOut : g_hr[srcSel ^ 1];
    float* d0 = dst + (b * 3 + 0) * HW;
    float* d1 = dst + (b * 3 + 1) * HW;
    float* d2 = dst + (b * 3 + 2) * HW;
    d0[pya * WW + px] = a01.x * invZa;
    d1[pya * WW + px] = a01.y * invZa;
    d2[pya * WW + px] = a2z.x * invZa;
    d0[(pya + 1) * WW + px] = b01.x * invZb;
    d1[(pya + 1) * WW + px] = b01.y * invZb;
    d2[(pya + 1) * WW + px] = b2z.x * invZb;
}

// ---------------- launcher ----------------
extern "C" void kernel_launch(void* const* d_in, const int* in_sizes, int n_in, void* d_out,
                              int out_size) {
    const float* x        = (const float*)d_in[0];
    const float* guidance = (const float*)d_in[1];
    const float* linear_w = (const float*)d_in[2];
    const float* linear_b = (const float*)d_in[3];
    const float* w1s      = (const float*)d_in[4];
    const float* b1s      = (const float*)d_in[5];
    const float* w2s      = (const float*)d_in[6];
    const float* b2s      = (const float*)d_in[7];
    const float* temps    = (const float*)d_in[8];
    const float* sigmas   = (const float*)d_in[9];
    float* out = (float*)d_out;

    cudaFuncSetAttribute(jbu_kernel, cudaFuncAttributeMaxDynamicSharedMemorySize, SMEM_JBU);

    linear_kernel<<<972, 256>>>(x, linear_w, linear_b);
    qproj_kernel<<<dim3(3136, 4), 128>>>(guidance, w1s, b1s, w2s, b2s);
    bicubic_kernel<<<4704, 256>>>();
    for (int st = 0; st < 4; st++) {
        jbu_kernel<<<dim3(7, 28, NB), dim3(32, 4), SMEM_JBU>>>(temps, sigmas, st, st & 1, out);
    }
}

// round 11
// speedup vs baseline: 2.7483x; 1.0686x over previous
#include <cuda_runtime.h>
#include <cuda_bf16.h>
#include <cuda_fp16.h>
#include <cstdint>
#include <math.h>

#define HH 224
#define WW 224
#define NB 8
#define CQ 32
#define HW (HH * WW)

// ---------------- scratch (static device globals; no allocation) ----------------
__device__ __nv_bfloat16 g_qb[4 * NB * HW * CQ];  // [st][b][h][w][c] bf16
__device__ float g_hr[2][NB * 3 * HW];            // ping-pong hr
__device__ float g_src[NB * 972];                 // linear output

// ---------------- generic helpers ----------------
__device__ __forceinline__ float htanh(float x) {
    float r;
    asm("tanh.approx.f32 %0, %1;" : "=f"(r) : "f"(x));
    return r;
}
__device__ __forceinline__ float ex2(float x) {
    float r;
    asm("ex2.approx.f32 %0, %1;" : "=f"(r) : "f"(x));
    return r;
}
__device__ __forceinline__ uint32_t smem_u32(const void* p) {
    uint32_t a;
    asm("{ .reg .u64 t; cvta.to.shared.u64 t, %1; cvt.u32.u64 %0, t; }" : "=r"(a) : "l"(p));
    return a;
}
__device__ __forceinline__ int refl(int i, int n) {
    if (i < 0) i = -i;
    if (i >= n) i = 2 * n - 2 - i;
    return i;
}
__device__ __forceinline__ float cubicw(float d) {
    d = fabsf(d);
    float d2 = d * d, d3 = d2 * d;
    if (d <= 1.f) return 1.25f * d3 - 2.25f * d2 + 1.f;
    if (d < 2.f) return -0.75f * d3 + 3.75f * d2 - 6.f * d + 3.f;
    return 0.f;
}

// ---------------- MMA / LDSM macros (validated in round 7) ----------------
#define LDM_X4(r0, r1, r2, r3, a)                                                \
    asm volatile("ldmatrix.sync.aligned.m8n8.x4.shared.b16 {%0,%1,%2,%3}, [%4];" \
                 : "=r"(r0), "=r"(r1), "=r"(r2), "=r"(r3) : "r"(a))
#define LDM_X2(r0, r1, a)                                                  \
    asm volatile("ldmatrix.sync.aligned.m8n8.x2.shared.b16 {%0,%1}, [%2];" \
                 : "=r"(r0), "=r"(r1) : "r"(a))
#define MMA_BF16(d, a, b)                                                  \
    asm volatile(                                                          \
        "mma.sync.aligned.m16n8k16.row.col.f32.bf16.bf16.f32 "             \
        "{%0,%1,%2,%3}, {%4,%5,%6,%7}, {%8,%9}, {%0,%1,%2,%3};"            \
        : "+f"((d)[0]), "+f"((d)[1]), "+f"((d)[2]), "+f"((d)[3])           \
        : "r"((a)[0]), "r"((a)[1]), "r"((a)[2]), "r"((a)[3]), "r"((b)[0]), \
          "r"((b)[1]))
#define MMA_F16(d, a, b)                                                   \
    asm volatile(                                                          \
        "mma.sync.aligned.m16n8k16.row.col.f32.f16.f16.f32 "               \
        "{%0,%1,%2,%3}, {%4,%5,%6,%7}, {%8,%9}, {%0,%1,%2,%3};"            \
        : "+f"((d)[0]), "+f"((d)[1]), "+f"((d)[2]), "+f"((d)[3])           \
        : "r"((a)[0]), "r"((a)[1]), "r"((a)[2]), "r"((a)[3]), "r"((b)[0]), \
          "r"((b)[1]))

// ---------------- kernel 1: linear ----------------
__global__ void linear_kernel(const float* __restrict__ x, const float* __restrict__ Wl,
                              const float* __restrict__ bl) {
    int wid = (blockIdx.x * blockDim.x + threadIdx.x) >> 5;
    int lane = threadIdx.x & 31;
    if (wid >= NB * 972) return;
    int b = wid / 972, j = wid % 972;
    const float* xr = x + b * 1000;
    const float* wr = Wl + j * 1000;
    float acc = 0.f;
    for (int c = lane; c < 1000; c += 32) acc += xr[c] * wr[c];
#pragma unroll
    for (int o = 16; o > 0; o >>= 1) acc += __shfl_down_sync(0xffffffffu, acc, o);
    if (lane == 0) g_src[wid] = acc + bl[j];
}

// ---------------- kernel 2: bicubic 18 -> 224 ----------------
__global__ void bicubic_kernel() {
    int idx = blockIdx.x * blockDim.x + threadIdx.x;
    if (idx >= NB * 3 * HW) return;
    int w = idx % WW;
    int h = (idx / WW) % HH;
    int bc = idx / HW;
    const float scale = 18.f / 224.f;
    float xi = (w + 0.5f) * scale - 0.5f;
    int x0 = (int)floorf(xi);
    float tx = xi - (float)x0;
    float wx[4];
    int ix[4];
#pragma unroll
    for (int k = 0; k < 4; k++) {
        wx[k] = cubicw(tx - (float)(k - 1));
        int ii = x0 + k - 1;
        ix[k] = ii < 0 ? 0 : (ii > 17 ? 17 : ii);
    }
    float yi = (h + 0.5f) * scale - 0.5f;
    int y0 = (int)floorf(yi);
    float ty = yi - (float)y0;
    float wy[4];
    int iy[4];
#pragma unroll
    for (int k = 0; k < 4; k++) {
        wy[k] = cubicw(ty - (float)(k - 1));
        int ii = y0 + k - 1;
        iy[k] = ii < 0 ? 0 : (ii > 17 ? 17 : ii);
    }
    const float* s = g_src + bc * 324;
    float acc = 0.f;
#pragma unroll
    for (int ky = 0; ky < 4; ky++) {
        float r = 0.f;
#pragma unroll
        for (int kx = 0; kx < 4; kx++) r += wx[kx] * s[iy[ky] * 18 + ix[kx]];
        acc += wy[ky] * r;
    }
    g_hr[0][idx] = acc;
}

// ------- kernel 3: range projection; layer1 fma + layer2 via mma.sync -------
__global__ void __launch_bounds__(128) qproj_kernel(const float* __restrict__ guid,
                                                    const float* __restrict__ w1s,
                                                    const float* __restrict__ b1s,
                                                    const float* __restrict__ w2s,
                                                    const float* __restrict__ b2s) {
    __shared__ __nv_bfloat16 s_h[128 * 40];
    __shared__ __nv_bfloat16 s_w2[32 * 40];
    __shared__ float s_w1[96], s_b1[32], s_b2[32];

    int st = blockIdx.y;
    int tid = threadIdx.x;
    int lane = tid & 31;
    int wrp = tid >> 5;

    if (tid < 96) s_w1[tid] = w1s[96 * st + tid];
    if (tid < 32) {
        s_b1[tid] = b1s[32 * st + tid];
        s_b2[tid] = b2s[32 * st + tid];
    }
    for (int i = tid; i < 1024; i += 128) {
        int n = i >> 5, k = i & 31;
        s_w2[n * 40 + k] = __float2bfloat16(w2s[1024 * st + n * 32 + k]);
    }

    int px = blockIdx.x * 128 + tid;
    int b = px / HW, hw = px % HW;
    float g0 = guid[(b * 3 + 0) * HW + hw];
    float g1 = guid[(b * 3 + 1) * HW + hw];
    float g2 = guid[(b * 3 + 2) * HW + hw];
    uint32_t* hrow = reinterpret_cast<uint32_t*>(&s_h[tid * 40]);
#pragma unroll
    for (int k2 = 0; k2 < 16; k2++) {
        float h01[2];
#pragma unroll
        for (int u = 0; u < 2; u++) {
            int k = 2 * k2 + u;
            float v = s_b1[k] + s_w1[k * 3] * g0 + s_w1[k * 3 + 1] * g1 + s_w1[k * 3 + 2] * g2;
            float uu = 0.7978845608f * v * (1.f + 0.044715f * v * v);
            h01[u] = 0.5f * v * (1.f + htanh(uu));
        }
        __nv_bfloat162 p = __floats2bfloat162_rn(h01[0], h01[1]);
        hrow[k2] = *reinterpret_cast<uint32_t*>(&p);
    }
    __syncthreads();

    uint32_t su_w2 = smem_u32(s_w2);
    int l16 = lane & 15;
    uint32_t bfr[4][2][2];
#pragma unroll
    for (int nt = 0; nt < 4; nt++)
#pragma unroll
        for (int ks = 0; ks < 2; ks++) {
            uint32_t a = su_w2 + ((nt * 8 + (l16 & 7)) * 40 + ks * 16 + ((l16 >> 3) & 1) * 8) * 2;
            LDM_X2(bfr[nt][ks][0], bfr[nt][ks][1], a);
        }

    uint32_t su_h = smem_u32(s_h);
    float d[2][4][4];
#pragma unroll
    for (int mt = 0; mt < 2; mt++)
#pragma unroll
        for (int nt = 0; nt < 4; nt++)
#pragma unroll
            for (int i = 0; i < 4; i++) d[mt][nt][i] = 0.f;

#pragma unroll
    for (int ks = 0; ks < 2; ks++) {
#pragma unroll
        for (int mt = 0; mt < 2; mt++) {
            int row = wrp * 32 + mt * 16 + ((lane >> 3) & 1) * 8 + (lane & 7);
            uint32_t a = su_h + (row * 40 + ks * 16 + (lane >> 4) * 8) * 2;
            uint32_t af[4];
            LDM_X4(af[0], af[1], af[2], af[3], a);
#pragma unroll
            for (int nt = 0; nt < 4; nt++) MMA_BF16(d[mt][nt], af, bfr[nt][ks]);
        }
    }

    uint32_t* qdst = reinterpret_cast<uint32_t*>(g_qb + (size_t)st * (NB * HW * CQ));
    int base_px = blockIdx.x * 128 + wrp * 32;
    int row_lo = lane >> 2;
    int col0 = (lane & 3) * 2;
#pragma unroll
    for (int mt = 0; mt < 2; mt++) {
#pragma unroll
        for (int nt = 0; nt < 4; nt++) {
            int ch = nt * 8 + col0;
            float bb0 = s_b2[ch], bb1 = s_b2[ch + 1];
            int p0 = base_px + mt * 16 + row_lo;
            __nv_bfloat162 lo = __floats2bfloat162_rn(d[mt][nt][0] + bb0, d[mt][nt][1] + bb1);
            __nv_bfloat162 hi = __floats2bfloat162_rn(d[mt][nt][2] + bb0, d[mt][nt][3] + bb1);
            qdst[p0 * 16 + ch / 2] = *reinterpret_cast<uint32_t*>(&lo);
            qdst[(p0 + 8) * 16 + ch / 2] = *reinterpret_cast<uint32_t*>(&hi);
        }
    }
}

// ---- kernel 4: JBU via tensor cores ----
// q tile: 22 rows x 24 cols, 80B/pixel (40 bf16)  -> 42240 B
// hr tile: 22 nbr rows x [8 ch][40 k] fp16        -> 14080 B
#define QROWP 1920
#define HROWP 640
#define SMEM_JBU (22 * QROWP + 22 * HROWP)  // 56320

__global__ void __launch_bounds__(256)
jbu_kernel(const float* __restrict__ temps, const float* __restrict__ sigmas, int stage,
           int srcSel, float* __restrict__ finalOut) {
    extern __shared__ char sm[];
    char* qs = sm;                // q tile
    char* hs = sm + 22 * QROWP;   // hr tile
    uint32_t qsu = smem_u32(qs);
    uint32_t hsu = smem_u32(hs);

    int tid = threadIdx.x;
    int lane = tid & 31;
    int wid = tid >> 5;
    int l16 = lane & 15;
    int b = blockIdx.z;
    int gx0 = blockIdx.x * 16 - 3;
    int gy0 = blockIdx.y * 16 - 3;

    // ---- fill q tile ----
    const uint4* qsrc = reinterpret_cast<const uint4*>(
        g_qb + (size_t)stage * (NB * HW * CQ) + (size_t)b * (HW * CQ));
    for (int idx = tid; idx < 22 * 24 * 4; idx += 256) {
        int c4 = idx & 3;
        int col = (idx >> 2) % 24;
        int r = idx / 96;
        int gr = refl(gy0 + r, HH);
        int gc = refl(gx0 + col, WW);
        *reinterpret_cast<uint4*>(qs + r * QROWP + col * 80 + c4 * 16) =
            qsrc[(gr * WW + gc) * 4 + c4];
    }
    // ---- fill hr tile: zero then (h0,h1,h2,1) ----
    for (int idx = tid; idx < 22 * HROWP / 4; idx += 256)
        reinterpret_cast<uint32_t*>(hs)[idx] = 0u;
    __syncthreads();
    const float* hsrc = g_hr[srcSel] + b * 3 * HW;
    for (int idx = tid; idx < 22 * 24; idx += 256) {
        int c = idx % 24;
        int r = idx / 24;
        int gr = refl(gy0 + r, HH);
        int gc = refl(gx0 + c, WW);
        int g = gr * WW + gc;
        __half* hp = reinterpret_cast<__half*>(hs + r * HROWP + c * 2);
        hp[0] = __float2half(hsrc[g]);
        hp[40] = __float2half(hsrc[HW + g]);
        hp[80] = __float2half(hsrc[2 * HW + g]);
        hp[120] = __float2half(1.0f);
    }
    __syncthreads();

    // ---- per-thread constants ----
    float t = fminf(fmaxf(__expf(temps[stage]), 1e-4f), 1e4f);
    float tl2e = t * 1.44269504088896f;
    float sig = sigmas[stage];
    float m2 = -(1.f / (2.f * sig * sig)) * (1.44269504088896f / 9.f);

    int qpx = lane >> 2;          // lo pixel; hi = qpx+8
    int cb = (lane & 3) * 2;
    // slots: 0,1: nt0 cols cb,cb+1 (lo px); 2,3: nt1 cols 8+cb,9+cb (lo);
    //        4,5: nt1 cols (hi px);         6,7: nt2 cols 16+cb,17+cb (hi)
    float addc[8], invc[8];
    {
        int cols[8] = {cb, cb + 1, 8 + cb, 9 + cb, 8 + cb, 9 + cb, 16 + cb, 17 + cb};
        int pxs[8] = {qpx, qpx, qpx, qpx, qpx + 8, qpx + 8, qpx + 8, qpx + 8};
#pragma unroll
        for (int i = 0; i < 8; i++) {
            int dj = cols[i] - pxs[i] - 3;
            bool v = (dj >= -3) && (dj <= 3);
            float a = m2 * (float)(dj * dj);
            addc[i] = v ? a : -10000.f;
            invc[i] = v ? ex2(-a) : 0.f;
        }
    }

    float* dst = (stage == 3) ? finalOut : g_hr[srcSel ^ 1];
    float* dc0 = dst + (b * 3 + 0) * HW;
    float* dc1 = dst + (b * 3 + 1) * HW;
    float* dc2 = dst + (b * 3 + 2) * HW;

#pragma unroll 1
    for (int rowIter = 0; rowIter < 2; rowIter++) {
        int y = wid * 2 + rowIter;  // pixel row 0..15
        // A score frags for center row
        uint32_t af[2][4];
#pragma unroll
        for (int ks = 0; ks < 2; ks++) {
            uint32_t a = qsu + (y + 3) * QROWP +
                         (3 + (lane & 7) + ((lane >> 3) & 1) * 8) * 80 + ks * 32 +
                         (lane >> 4) * 16;
            LDM_X4(af[ks][0], af[ks][1], af[ks][2], af[ks][3], a);
        }

        float dout[4] = {0.f, 0.f, 0.f, 0.f};
        float z1lo = 0.f, z1hi = 0.f;

#pragma unroll 1
        for (int di = -3; di <= 3; di++) {
            int NR = y + 3 + di;
            float di2m2 = m2 * (float)(di * di);
            float w[8];
            uint32_t wa0[4], wa1[4];
            // --- nt0: lo px slots 0,1 ---
            {
                float dnt[4] = {0.f, 0.f, 0.f, 0.f};
#pragma unroll
                for (int ks = 0; ks < 2; ks++) {
                    uint32_t bf[2];
                    uint32_t a = qsu + NR * QROWP + (0 * 8 + (l16 & 7)) * 80 + ks * 32 +
                                 ((l16 >> 3) & 1) * 16;
                    LDM_X2(bf[0], bf[1], a);
                    MMA_BF16(dnt, af[ks], bf);
                }
                w[0] = ex2(fmaf(dnt[0], tl2e, addc[0]) + di2m2);
                w[1] = ex2(fmaf(dnt[1], tl2e, addc[1]) + di2m2);
                __half2 p = __floats2half2_rn(w[0], w[1]);
                wa0[0] = *reinterpret_cast<uint32_t*>(&p);
                wa0[1] = 0u;  // nt0 hi-px: statically invalid
            }
            // --- nt1: slots 2,3 (lo), 4,5 (hi) ---
            {
                float dnt[4] = {0.f, 0.f, 0.f, 0.f};
#pragma unroll
                for (int ks = 0; ks < 2; ks++) {
                    uint32_t bf[2];
                    uint32_t a = qsu + NR * QROWP + (8 + (l16 & 7)) * 80 + ks * 32 +
                                 ((l16 >> 3) & 1) * 16;
                    LDM_X2(bf[0], bf[1], a);
                    MMA_BF16(dnt, af[ks], bf);
                }
                w[2] = ex2(fmaf(dnt[0], tl2e, addc[2]) + di2m2);
                w[3] = ex2(fmaf(dnt[1], tl2e, addc[3]) + di2m2);
                w[4] = ex2(fmaf(dnt[2], tl2e, addc[4]) + di2m2);
                w[5] = ex2(fmaf(dnt[3], tl2e, addc[5]) + di2m2);
                __half2 plo = __floats2half2_rn(w[2], w[3]);
                __half2 phi = __floats2half2_rn(w[4], w[5]);
                wa0[2] = *reinterpret_cast<uint32_t*>(&plo);
                wa0[3] = *reinterpret_cast<uint32_t*>(&phi);
            }
            // --- nt2: hi px slots 6,7 ---
            {
                float dnt[4] = {0.f, 0.f, 0.f, 0.f};
#pragma unroll
                for (int ks = 0; ks < 2; ks++) {
                    uint32_t bf[2];
                    uint32_t a = qsu + NR * QROWP + (16 + (l16 & 7)) * 80 + ks * 32 +
                                 ((l16 >> 3) & 1) * 16;
                    LDM_X2(bf[0], bf[1], a);
                    MMA_BF16(dnt, af[ks], bf);
                }
                w[6] = ex2(fmaf(dnt[2], tl2e, addc[6]) + di2m2);
                w[7] = ex2(fmaf(dnt[3], tl2e, addc[7]) + di2m2);
                __half2 p = __floats2half2_rn(w[6], w[7]);
                wa1[0] = 0u;  // nt2 lo-px: statically invalid
                wa1[1] = *reinterpret_cast<uint32_t*>(&p);
                wa1[2] = 0u;
                wa1[3] = 0u;
            }
            // --- Z1 (range-only sum): e = w * invsp ---
            float invdi = ex2(-di2m2);
            z1lo += invdi * (w[0] * invc[0] + w[1] * invc[1] + w[2] * invc[2] + w[3] * invc[3]);
            z1hi += invdi * (w[4] * invc[4] + w[5] * invc[5] + w[6] * invc[6] + w[7] * invc[7]);
            // --- hr-apply MMAs ---
#pragma unroll
            for (int ks = 0; ks < 2; ks++) {
                uint32_t hb[2];
                uint32_t a = hsu + NR * HROWP + (l16 & 7) * 80 + ks * 32 +
                             ((l16 >> 3) & 1) * 16;
                LDM_X2(hb[0], hb[1], a);
                MMA_F16(dout, (ks == 0 ? wa0 : wa1), hb);
            }
        }

        // ---- reduce + store ----
        z1lo += __shfl_xor_sync(0xffffffffu, z1lo, 1);
        z1lo += __shfl_xor_sync(0xffffffffu, z1lo, 2);
        z1hi += __shfl_xor_sync(0xffffffffu, z1hi, 1);
        z1hi += __shfl_xor_sync(0xffffffffu, z1hi, 2);
        int zsrc = (lane & ~3) | 1;
        float Zlo = __shfl_sync(0xffffffffu, dout[1], zsrc);
        float Zhi = __shfl_sync(0xffffffffu, dout[3], zsrc);
        float invZlo = 1.f / fmaxf(Zlo, 1e-7f * z1lo);
        float invZhi = 1.f / fmaxf(Zhi, 1e-7f * z1hi);

        int ygl = blockIdx.y * 16 + y;
        int xlo = blockIdx.x * 16 + qpx;
        int o = ygl * WW + xlo;
        if ((lane & 3) == 0) {
            dc0[o] = dout[0] * invZlo;
            dc1[o] = dout[1] * invZlo;
            dc0[o + 8] = dout[2] * invZhi;
            dc1[o + 8] = dout[3] * invZhi;
        } else if ((lane & 3) == 1) {
            dc2[o] = dout[0] * invZlo;
            dc2[o + 8] = dout[2] * invZhi;
        }
    }
}

// ---------------- launcher ----------------
extern "C" void kernel_launch(void* const* d_in, const int* in_sizes, int n_in, void* d_out,
                              int out_size) {
    const float* x        = (const float*)d_in[0];
    const float* guidance = (const float*)d_in[1];
    const float* linear_w = (const float*)d_in[2];
    const float* linear_b = (const float*)d_in[3];
    const float* w1s      = (const float*)d_in[4];
    const float* b1s      = (const float*)d_in[5];
    const float* w2s      = (const float*)d_in[6];
    const float* b2s      = (const float*)d_in[7];
    const float* temps    = (const float*)d_in[8];
    const float* sigmas   = (const float*)d_in[9];
    float* out = (float*)d_out;

    cudaFuncSetAttribute(jbu_kernel, cudaFuncAttributeMaxDynamicSharedMemorySize, SMEM_JBU);

    linear_kernel<<<972, 256>>>(x, linear_w, linear_b);
    qproj_kernel<<<dim3(3136, 4), 128>>>(guidance, w1s, b1s, w2s, b2s);
    bicubic_kernel<<<4704, 256>>>();
    for (int st = 0; st < 4; st++) {
        jbu_kernel<<<dim3(14, 14, NB), 256, SMEM_JBU>>>(temps, sigmas, st, st & 1, out);
    }
}